// round 11
// baseline (speedup 1.0000x reference)
#include <cuda_runtime.h>
#include <cuda_bf16.h>

#define NSAMPLE 32
#define NPTS 4096
#define MAXB 8
#define BLOCK_THREADS 64
#define WARPS_PER_BLOCK (BLOCK_THREADS / 32)
#define SCR_SLOTS 128   // per-warp scratch (max slot overshoot 94)
#define PAIRS_PER_B (NPTS / 2)   // 2048 lane-pair entries per batch

// Lane-interleaved packed layout: entry s (chunk c = s>>5, lane l = s&31)
// holds the pair (n0 = c*64 + l, n1 = n0 + 32):
//   g_pkA[s] = (x_n0, x_n1, y_n0, y_n1)   -> px, py as aligned f32x2 pairs
//   g_pkB[s] = (z_n0, z_n1, w_n0, w_n1)   -> pz, pw as aligned f32x2 pairs
// +32 pad so the depth-2 prefetch may harmlessly overrun on the last iter.
__device__ float4 g_pkA[MAXB * PAIRS_PER_B + 32];
__device__ float4 g_pkB[MAXB * PAIRS_PER_B + 32];

// ---- f32x2 packed helpers (sm_103a), arithmetic FROZEN from round 10.
__device__ __forceinline__ unsigned long long pk2(float lo, float hi) {
    unsigned long long r;
    asm("mov.b64 %0, {%1, %2};" : "=l"(r) : "f"(lo), "f"(hi));
    return r;
}
__device__ __forceinline__ void upk2(unsigned long long v, float& lo, float& hi) {
    asm("mov.b64 {%0, %1}, %2;" : "=f"(lo), "=f"(hi) : "l"(v));
}
__device__ __forceinline__ unsigned long long mul2(unsigned long long a,
                                                   unsigned long long b) {
    unsigned long long r;
    asm("mul.rn.f32x2 %0, %1, %2;" : "=l"(r) : "l"(a), "l"(b));
    return r;
}
__device__ __forceinline__ unsigned long long add2(unsigned long long a,
                                                   unsigned long long b) {
    unsigned long long r;
    asm("add.rn.f32x2 %0, %1, %2;" : "=l"(r) : "l"(a), "l"(b));
    return r;
}

// Pre-pass: build the lane-interleaved pair arrays. |p|^2 expression FROZEN:
// rn((rn(x*x) + rn(y*y)) + rn(z*z)), no FMA contraction.
__global__ void pack_kernel(const float* __restrict__ xyz, int total_pairs) {
    const int j = blockIdx.x * blockDim.x + threadIdx.x;
    if (j >= total_pairs) return;
    const int b = j / PAIRS_PER_B;
    const int s = j - b * PAIRS_PER_B;
    const int n0 = b * NPTS + ((s >> 5) << 6) + (s & 31);
    const int n1 = n0 + 32;

    const float x0 = xyz[n0 * 3 + 0], y0 = xyz[n0 * 3 + 1], z0 = xyz[n0 * 3 + 2];
    const float x1 = xyz[n1 * 3 + 0], y1 = xyz[n1 * 3 + 1], z1 = xyz[n1 * 3 + 2];
    const float w0 = __fadd_rn(__fadd_rn(__fmul_rn(x0, x0), __fmul_rn(y0, y0)),
                               __fmul_rn(z0, z0));
    const float w1 = __fadd_rn(__fadd_rn(__fmul_rn(x1, x1), __fmul_rn(y1, y1)),
                               __fmul_rn(z1, z1));
    g_pkA[j] = make_float4(x0, x1, y0, y1);
    g_pkB[j] = make_float4(z0, z1, w0, w1);
}

// One warp per query, 64 points/iter, depth-2 pointer prefetch. The packed
// layout delivers px/py/pz/pw as register-pair-aligned f32x2 operands straight
// from two LDG.128s — the round-10 pk2 MOV overhead is gone. Distance math is
// instruction-for-instruction identical to round 10 (frozen, rel_err
// 7.915904e-4). Deferred smem emission + select epilogue as in rounds 9-10.
__global__ void ball_query_kernel(const float* __restrict__ xyz,
                                  float* __restrict__ out) {
    __shared__ float scr[WARPS_PER_BLOCK][SCR_SLOTS];

    const int lane = threadIdx.x & 31;
    const int w = threadIdx.x >> 5;
    const int gw = blockIdx.x * WARPS_PER_BLOCK + w;
    const int b = gw >> 12;          // / NPTS

    const ulonglong2* __restrict__ pA =
        reinterpret_cast<const ulonglong2*>(g_pkA) + (size_t)b * PAIRS_PER_B + lane;
    const ulonglong2* __restrict__ pB =
        reinterpret_cast<const ulonglong2*>(g_pkB) + (size_t)b * PAIRS_PER_B + lane;

    // Query point straight from xyz; qw uses the frozen |q|^2 expression.
    const float qx = xyz[gw * 3 + 0];
    const float qy = xyz[gw * 3 + 1];
    const float qz = xyz[gw * 3 + 2];
    const float qw = __fadd_rn(__fadd_rn(__fmul_rn(qx, qx), __fmul_rn(qy, qy)),
                               __fmul_rn(qz, qz));
    const unsigned long long qxp = pk2(qx, qx);
    const unsigned long long qyp = pk2(qy, qy);
    const unsigned long long qzp = pk2(qz, qz);
    const unsigned long long qwp = pk2(qw, qw);
    const unsigned long long M2  = pk2(-2.0f, -2.0f);

    const unsigned mlt = (1u << lane) - 1u;
    const float r2 = 0.04f;          // f32 promotion of 0.2*0.2
    int count = 0;

    ulonglong2 A = pA[0];            // prefetch chunk-pair 0
    ulonglong2 Bv = pB[0];
    pA += 32; pB += 32;

    float f0 = (float)lane;          // emission values, +64.0f per iter
    float f1 = (float)(lane + 32);

    for (int it = 0; it < NPTS / 64; ++it) {
        const unsigned long long px = A.x;   // (x_n0, x_n1)
        const unsigned long long py = A.y;   // (y_n0, y_n1)
        const unsigned long long pz = Bv.x;  // (z_n0, z_n1)
        const unsigned long long pw = Bv.y;  // (w_n0, w_n1)
        A = pA[0];                   // prefetch next pair (pad catches overrun)
        Bv = pB[0];
        pA += 32; pB += 32;

        const unsigned long long dot =
            add2(add2(mul2(qxp, px), mul2(qyp, py)), mul2(qzp, pz));
        const unsigned long long d2p = add2(add2(qwp, pw), mul2(dot, M2));

        float d20, d21;
        upk2(d2p, d20, d21);         // register aliasing at SASS level

        const bool h0 = d20 < r2;
        const bool h1 = d21 < r2;
        const unsigned bal0 = __ballot_sync(0xffffffffu, h0);
        const unsigned bal1 = __ballot_sync(0xffffffffu, h1);

        if (h0) scr[w][count + __popc(bal0 & mlt)] = f0;
        const int cn = count + __popc(bal0);
        if (h1) scr[w][cn + __popc(bal1 & mlt)] = f1;
        count = cn + __popc(bal1);

        f0 += 64.0f;
        f1 += 64.0f;

        if (count >= NSAMPLE) break;  // count is warp-uniform
    }

    __syncwarp();                     // order scratch stores within the warp
    const int sel = (lane < count) ? lane : 0;  // scr[0] == smallest hit
    out[(size_t)gw * NSAMPLE + lane] = scr[w][sel];
}

extern "C" void kernel_launch(void* const* d_in, const int* in_sizes, int n_in,
                              void* d_out, int out_size) {
    const float* xyz = (const float*)d_in[0];  // 'xyz' (B, N, 3) float32
    // d_in[1] ('xyz_new') is unused by the reference (it queries xyz vs xyz).
    const int B = in_sizes[0] / (NPTS * 3);    // 8
    float* out = (float*)d_out;

    const int total_pairs = B * PAIRS_PER_B;   // 16384
    pack_kernel<<<(total_pairs + 255) / 256, 256>>>(xyz, total_pairs);

    const int blocks = (B * NPTS) / WARPS_PER_BLOCK;  // 16384
    ball_query_kernel<<<blocks, BLOCK_THREADS>>>(xyz, out);
}

// round 12
// speedup vs baseline: 1.3182x; 1.3182x over previous
#include <cuda_runtime.h>
#include <cuda_bf16.h>

#define NSAMPLE 32
#define NPTS 4096
#define MAXB 8
#define BLOCK_THREADS 64
#define WARPS_PER_BLOCK (BLOCK_THREADS / 32)
#define SCR_SLOTS 192   // max slot overshoot: 31 + 128 = 159

// Packed points: (x, y, z, |p|^2), +128 pad so the depth-4 prefetch may
// harmlessly overrun on the final iteration (loaded, never consumed).
__device__ float4 g_pts[MAXB * NPTS + 128];

// ---- f32x2 packed helpers (sm_103a), arithmetic FROZEN from round 10
// (rel_err 7.915904e-4 with seed-deterministic inputs).
__device__ __forceinline__ unsigned long long pk2(float lo, float hi) {
    unsigned long long r;
    asm("mov.b64 %0, {%1, %2};" : "=l"(r) : "f"(lo), "f"(hi));
    return r;
}
__device__ __forceinline__ void upk2(unsigned long long v, float& lo, float& hi) {
    asm("mov.b64 {%0, %1}, %2;" : "=f"(lo), "=f"(hi) : "l"(v));
}
__device__ __forceinline__ unsigned long long mul2(unsigned long long a,
                                                   unsigned long long b) {
    unsigned long long r;
    asm("mul.rn.f32x2 %0, %1, %2;" : "=l"(r) : "l"(a), "l"(b));
    return r;
}
__device__ __forceinline__ unsigned long long add2(unsigned long long a,
                                                   unsigned long long b) {
    unsigned long long r;
    asm("add.rn.f32x2 %0, %1, %2;" : "=l"(r) : "l"(a), "l"(b));
    return r;
}

// Pre-pass: pack xyz + squared norm (frozen expression, no FMA contraction).
__global__ void pack_kernel(const float* __restrict__ xyz, int total) {
    const int i = blockIdx.x * blockDim.x + threadIdx.x;
    if (i < total) {
        const float x = xyz[i * 3 + 0];
        const float y = xyz[i * 3 + 1];
        const float z = xyz[i * 3 + 2];
        const float sq = __fadd_rn(__fadd_rn(__fmul_rn(x, x), __fmul_rn(y, y)),
                                   __fmul_rn(z, z));
        g_pts[i] = make_float4(x, y, z, sq);
    }
}

// One warp per query, 128 points/iter (4 chunks), depth-4 register prefetch,
// f32x2 packed distance math — the ROUND-10 body replicated twice per
// iteration so loop control / pointer / break costs amortize over 2x points.
// All fp operations bit-identical to round 10. Ballot-ordered deferred smem
// emission; epilogue select does copy + truncate + pad-with-first in one store.
__global__ void ball_query_kernel(float* __restrict__ out) {
    __shared__ float scr[WARPS_PER_BLOCK][SCR_SLOTS];

    const int lane = threadIdx.x & 31;
    const int w = threadIdx.x >> 5;
    const int gw = blockIdx.x * WARPS_PER_BLOCK + w;
    const int b = gw >> 12;          // / NPTS

    const float4* __restrict__ p = g_pts + (size_t)b * NPTS;

    const float4 q = g_pts[gw];      // query point (gw == b*NPTS + m)
    const unsigned long long qxp = pk2(q.x, q.x);
    const unsigned long long qyp = pk2(q.y, q.y);
    const unsigned long long qzp = pk2(q.z, q.z);
    const unsigned long long qwp = pk2(q.w, q.w);
    const unsigned long long M2  = pk2(-2.0f, -2.0f);

    const unsigned mlt = (1u << lane) - 1u;
    const float r2 = 0.04f;          // f32 promotion of 0.2*0.2
    int count = 0;

    float4 s0 = p[lane];             // prefetch 4 chunks (128 points)
    float4 s1 = p[32 + lane];
    float4 s2 = p[64 + lane];
    float4 s3 = p[96 + lane];
    p += 128;

    float f0 = (float)lane;          // emission values, +128.0f per iter
    float f1 = (float)(lane + 32);
    float f2 = (float)(lane + 64);
    float f3 = (float)(lane + 96);

    for (int it = 0; it < NPTS / 128; ++it) {
        const float4 c0 = s0, c1 = s1, c2 = s2, c3 = s3;
        s0 = p[lane];                // final-iter overrun lands in the pad
        s1 = p[32 + lane];
        s2 = p[64 + lane];
        s3 = p[96 + lane];
        p += 128;

        // pair (chunk0, chunk1) — round-10 body, verbatim
        const unsigned long long pxA = pk2(c0.x, c1.x);
        const unsigned long long pyA = pk2(c0.y, c1.y);
        const unsigned long long pzA = pk2(c0.z, c1.z);
        const unsigned long long pwA = pk2(c0.w, c1.w);
        const unsigned long long dotA =
            add2(add2(mul2(qxp, pxA), mul2(qyp, pyA)), mul2(qzp, pzA));
        const unsigned long long d2A = add2(add2(qwp, pwA), mul2(dotA, M2));
        float d20, d21;
        upk2(d2A, d20, d21);

        // pair (chunk2, chunk3)
        const unsigned long long pxB = pk2(c2.x, c3.x);
        const unsigned long long pyB = pk2(c2.y, c3.y);
        const unsigned long long pzB = pk2(c2.z, c3.z);
        const unsigned long long pwB = pk2(c2.w, c3.w);
        const unsigned long long dotB =
            add2(add2(mul2(qxp, pxB), mul2(qyp, pyB)), mul2(qzp, pzB));
        const unsigned long long d2B = add2(add2(qwp, pwB), mul2(dotB, M2));
        float d22, d23;
        upk2(d2B, d22, d23);

        const bool h0 = d20 < r2;
        const bool h1 = d21 < r2;
        const bool h2 = d22 < r2;
        const bool h3 = d23 < r2;
        const unsigned bal0 = __ballot_sync(0xffffffffu, h0);
        const unsigned bal1 = __ballot_sync(0xffffffffu, h1);
        const unsigned bal2 = __ballot_sync(0xffffffffu, h2);
        const unsigned bal3 = __ballot_sync(0xffffffffu, h3);

        if (h0) scr[w][count + __popc(bal0 & mlt)] = f0;
        int cn = count + __popc(bal0);
        if (h1) scr[w][cn + __popc(bal1 & mlt)] = f1;
        cn += __popc(bal1);
        if (h2) scr[w][cn + __popc(bal2 & mlt)] = f2;
        cn += __popc(bal2);
        if (h3) scr[w][cn + __popc(bal3 & mlt)] = f3;
        count = cn + __popc(bal3);

        f0 += 128.0f;
        f1 += 128.0f;
        f2 += 128.0f;
        f3 += 128.0f;

        if (count >= NSAMPLE) break;  // count is warp-uniform
    }

    __syncwarp();                     // order scratch stores within the warp
    const int sel = (lane < count) ? lane : 0;  // scr[0] == smallest hit
    out[(size_t)gw * NSAMPLE + lane] = scr[w][sel];
}

extern "C" void kernel_launch(void* const* d_in, const int* in_sizes, int n_in,
                              void* d_out, int out_size) {
    const float* xyz = (const float*)d_in[0];  // 'xyz' (B, N, 3) float32
    // d_in[1] ('xyz_new') is unused by the reference (it queries xyz vs xyz).
    const int B = in_sizes[0] / (NPTS * 3);    // 8
    float* out = (float*)d_out;

    const int total = B * NPTS;  // 32768
    pack_kernel<<<(total + 255) / 256, 256>>>(xyz, total);

    const int blocks = total / WARPS_PER_BLOCK;  // 16384
    ball_query_kernel<<<blocks, BLOCK_THREADS>>>(out);
}